// round 11
// baseline (speedup 1.0000x reference)
#include <cuda_runtime.h>

#define B 128
#define DF 2048
#define KSPLIT 64
#define KCHUNK 32           // DF / KSPLIT
#define NBLOCKS 128
#define NTHREADS 256
#define LDA 132             // padded SMEM row stride (even -> float2 aligned)

// Scratch (static device globals; no allocation).
__device__ float g_Gp[KSPLIT * B * B];   // split-K partial Gram, UPPER tiles only (4MB)
__device__ float g_G[B * B];             // reduced full Gram
__device__ float g_part[NBLOCKS];        // per-block loss partials
__device__ unsigned g_bar[2];            // monotonic barrier counters (never reset)
__device__ unsigned g_fin;               // monotonic finalize counter (never reset)

// Monotonic grid barrier: no reset across graph replays (2^32 % 128 == 0).
__device__ __forceinline__ void grid_barrier(int which) {
    __syncthreads();
    if (threadIdx.x == 0) {
        __threadfence();                                   // release
        unsigned old = atomicAdd(&g_bar[which], 1u);
        unsigned target = old - (old & (NBLOCKS - 1u)) + NBLOCKS;
        while ((int)(*(volatile unsigned*)&g_bar[which] - target) < 0) {
            __nanosleep(64);
        }
        __threadfence();                                   // acquire
    }
    __syncthreads();
}

__global__ __launch_bounds__(NTHREADS) void fused_angle_loss(
    const float* __restrict__ X, float* __restrict__ out) {

    __shared__ float smemBuf[KCHUNK * LDA];   // 16.9KB, reused across phases
    const int b = blockIdx.x;
    const int t = threadIdx.x;

    // ================= Phase 1: symmetric split-K Gram ======================
    // G symmetric: only 10 upper 32x32 tiles of the 4x4 tile grid computed.
    // 10 tiles x 64 k-chunks = 640 units = 5 per block. Block b: z = b&63,
    // tile set ts = b>>6 (even/odd tiles of the 10). X k-slice (128 rows x
    // 32 k = 16KB) loaded ONCE into SMEM; all 5 tiles computed from it.
    {
        const int z  = b & 63;
        const int ts = b >> 6;
        const int kB = z * KCHUNK;

        // tile lists: set0 covers (0,0),(0,2),(1,1),(1,3),(2,3)
        //             set1 covers (0,1),(0,3),(1,2),(2,2),(3,3)
        const int tiA[5] = {0, 0, 1, 1, 2}, tjA[5] = {0, 2, 1, 3, 3};
        const int tiB[5] = {0, 0, 1, 2, 3}, tjB[5] = {1, 3, 2, 2, 3};

        float* As = smemBuf;    // [k][row] k-major, stride LDA

        // Load full X k-slice: 128 rows x 32 k = 1024 float4; 4 per thread.
#pragma unroll
        for (int it = 0; it < 4; it++) {
            const int i   = t + it * NTHREADS;   // 0..1023
            const int row = i >> 3;              // 0..127
            const int kq  = (i & 7) * 4;         // 0..28
            float4 v = *(const float4*)(X + (size_t)row * DF + kB + kq);
            As[(kq + 0) * LDA + row] = v.x; As[(kq + 1) * LDA + row] = v.y;
            As[(kq + 2) * LDA + row] = v.z; As[(kq + 3) * LDA + row] = v.w;
        }
        __syncthreads();

        const int ty = t >> 4;            // 0..15
        const int tx = t & 15;            // 0..15
        int rb[5], cb[5];
#pragma unroll
        for (int u = 0; u < 5; u++) {
            rb[u] = (ts ? tiB[u] : tiA[u]) * 32 + 2 * ty;
            cb[u] = (ts ? tjB[u] : tjA[u]) * 32 + 2 * tx;
        }

        float acc[5][4] = {};
#pragma unroll 8
        for (int k = 0; k < KCHUNK; k++) {
            const float* row = &As[k * LDA];
#pragma unroll
            for (int u = 0; u < 5; u++) {
                float2 a  = *(const float2*)&row[rb[u]];
                float2 bv = *(const float2*)&row[cb[u]];
                acc[u][0] = fmaf(a.x, bv.x, acc[u][0]);
                acc[u][1] = fmaf(a.x, bv.y, acc[u][1]);
                acc[u][2] = fmaf(a.y, bv.x, acc[u][2]);
                acc[u][3] = fmaf(a.y, bv.y, acc[u][3]);
            }
        }

        float* dst = g_Gp + (size_t)z * (B * B);
#pragma unroll
        for (int u = 0; u < 5; u++) {
            *(float2*)&dst[(rb[u] + 0) * B + cb[u]] = make_float2(acc[u][0], acc[u][1]);
            *(float2*)&dst[(rb[u] + 1) * B + cb[u]] = make_float2(acc[u][2], acc[u][3]);
        }
    }

    grid_barrier(0);

    // ========== Phase 2: split-K reduce + mirror (all 128 blocks) ===========
    // 4096 float4 outputs / 128 blocks = 32 per block. 256 threads: f4c=t&31,
    // z-group zg=t>>5 sums 8 layers (transposed reads below the diagonal),
    // then t<32 combines the 8 partials in fixed zg order (deterministic).
    {
        float4* part = (float4*)smemBuf;           // [8][32] float4 = 4KB
        const int f4c = t & 31;
        const int zg  = t >> 5;
        const int f4  = b * 32 + f4c;
        const int r   = f4 >> 5;                   // output row
        const int c0  = (f4 & 31) * 4;             // output cols c0..c0+3
        const bool up = (r >> 5) <= (c0 >> 5);     // tile stored directly?

        float4 s = make_float4(0.f, 0.f, 0.f, 0.f);
#pragma unroll
        for (int zz = 0; zz < 8; zz++) {
            const float* L = g_Gp + (size_t)(zg * 8 + zz) * (B * B);
            if (up) {
                float4 v = __ldcg((const float4*)&L[r * B + c0]);
                s.x += v.x; s.y += v.y; s.z += v.z; s.w += v.w;
            } else {                               // mirror: G[r][c] = G[c][r]
                s.x += __ldcg(&L[(c0 + 0) * B + r]);
                s.y += __ldcg(&L[(c0 + 1) * B + r]);
                s.z += __ldcg(&L[(c0 + 2) * B + r]);
                s.w += __ldcg(&L[(c0 + 3) * B + r]);
            }
        }
        part[zg * 32 + f4c] = s;
        __syncthreads();
        if (t < 32) {
            float4 rsum = part[t];
#pragma unroll
            for (int zg2 = 1; zg2 < 8; zg2++) {
                float4 v = part[zg2 * 32 + t];
                rsum.x += v.x; rsum.y += v.y; rsum.z += v.z; rsum.w += v.w;
            }
            ((float4*)g_G)[f4] = rsum;
        }
    }

    grid_barrier(1);

    // ======================= Phase 3: loss (all 128 blocks) =================
    // b = group*8 + slice. Group g=(target,sub); slice s -> pairs
    // (j0,j1) = (16p+s, 16p+s+8) for the 7 p != target.
    // ALL global loads issued in one batch up front (single L2 round).
    {
        const int g    = b >> 3;
        const int s    = b & 7;
        const int tgt  = g >> 1;
        const int sb   = g & 1;
        const int base = tgt * 16 + sb * 8;
        const int k    = t & 127;
        const int h    = t >> 7;

        float* sS    = smemBuf;          // [128] mean row-dot (already /8)
        float* sInv  = smemBuf + 128;    // [128] 1/norm
        float* sDiag = smemBuf + 256;    // [128] G[k][k]
        float* red   = smemBuf + 384;    // [8]
        int*   sFlag = (int*)(smemBuf + 392);

        // ---- batched loads (independent; one MLP window) ----
        float rowv[8];
        float gv0[4], gv1[4];
        float dia = 0.f;

        if (h == 0) {
#pragma unroll
            for (int i = 0; i < 8; i++) rowv[i] = __ldcg(&g_G[(base + i) * B + k]);
        } else {
            dia = __ldcg(&g_G[k * B + k]);
        }
#pragma unroll
        for (int pi = 0; pi < 4; pi++) {
            const int p = h * 4 + pi;
            const int j0 = p * 16 + s;
            gv0[pi] = __ldcg(&g_G[j0 * B + k]);         // loaded even if p==tgt
            gv1[pi] = __ldcg(&g_G[(j0 + 8) * B + k]);
        }
        __syncthreads();    // phase-2 smem reads complete before overwrite

        if (h == 0) {
            float sk = ((rowv[0] + rowv[1]) + (rowv[2] + rowv[3]))
                     + ((rowv[4] + rowv[5]) + (rowv[6] + rowv[7]));
            sS[k] = sk * 0.125f;
        } else {
            sDiag[k] = dia;
        }
        __syncthreads();

        float q = 0.f;
#pragma unroll
        for (int i = 0; i < 8; i++) q += sS[base + i];
        q *= 0.125f;

        if (h == 0) {
            const float n2 = sDiag[k] - 2.f * sS[k] + q;
            const float nr = sqrtf(fmaxf(n2, 0.f));
            sInv[k] = 1.f / fmaxf(nr, 1e-12f);
        }
        __syncthreads();

        const float sk   = sS[k];
        const float invk = sInv[k];
        float acc = 0.f;
#pragma unroll
        for (int pi = 0; pi < 4; pi++) {
            const int p = h * 4 + pi;
            if (p == tgt) continue;
            const int j0 = p * 16 + s;
            const int j1 = j0 + 8;
            const float a0 = (gv0[pi] - sS[j0] - sk + q) * (sInv[j0] * invk);
            const float a1 = (gv1[pi] - sS[j1] - sk + q) * (sInv[j1] * invk);
            acc += fabsf(a0 - a1);
        }

        // Deterministic block reduction over 256 threads.
#pragma unroll
        for (int o = 16; o > 0; o >>= 1) acc += __shfl_down_sync(0xffffffffu, acc, o);
        if ((t & 31) == 0) red[t >> 5] = acc;
        __syncthreads();

        if (t == 0) {
            float sum = 0.f;
#pragma unroll
            for (int w = 0; w < 8; w++) sum += red[w];
            g_part[b] = sum;
            __threadfence();
            unsigned old = atomicAdd(&g_fin, 1u);
            sFlag[0] = ((old & (NBLOCKS - 1u)) == (NBLOCKS - 1u)) ? 1 : 0;
        }
        __syncthreads();

        // ---- parallel deterministic finalize by the last-arriving block ----
        if (sFlag[0]) {
            float v = (t < NBLOCKS) ? __ldcg(&g_part[t]) : 0.f;
#pragma unroll
            for (int o = 16; o > 0; o >>= 1) v += __shfl_down_sync(0xffffffffu, v, o);
            if ((t & 31) == 0) red[t >> 5] = v;
            __syncthreads();
            if (t == 0) {
                float tot = ((red[0] + red[1]) + (red[2] + red[3]));
                out[0] = tot * (1.0f / 114688.0f);
            }
        }
    }
}

extern "C" void kernel_launch(void* const* d_in, const int* in_sizes, int n_in,
                              void* d_out, int out_size) {
    const float* X = (const float*)d_in[0];   // [128, 2048] fp32
    float* out = (float*)d_out;               // scalar loss

    fused_angle_loss<<<NBLOCKS, NTHREADS>>>(X, out);
}